// round 9
// baseline (speedup 1.0000x reference)
#include <cuda_runtime.h>
#include <math.h>

#define BMAX     256
#define SIGLEN   178
#define NFR      43
#define NFQ      33
#define NPQ      (NFQ*NFR)
#define COUT     64
#define CONV_OUT 89
#define NSTEP    12          // ceil(89/8) j-steps

#define PHI_N    (89*4*7*64)
#define AY_N     (89*4*7)
#define TW_N     (33*7)

__device__ __align__(16) float g_spec [NPQ * BMAX];          // [p*43+q][b]
__device__ __align__(16) float g_phi  [PHI_N];               // [j][qt][ky][c]
__device__ __align__(16) float g_ay   [AY_N];                // [r][pt][ky]
__device__ __align__(16) float g_twid [33*14];
__device__ __align__(16) float g_theta[(size_t)89*89*16*64]; // [r][j][tap][c]
__device__ __align__(16) float g_part [(size_t)CONV_OUT * BMAX * COUT]; // [r][b][c]

// ---- shared index helpers --------------------------------------------------
__device__ __forceinline__ int q0raw(int j) {
    float sx = (2 * j - 3 + 0.5f) * (43.0f / 178.0f) - 0.5f;
    sx = fminf(fmaxf(sx, 0.f), 42.f);
    return (int)sx;
}
__device__ __forceinline__ int q0f(int j) { int q = q0raw(j); return q > 39 ? 39 : q; }
__device__ __forceinline__ int p0f(int r) {
    float sy = (2 * r - 3 + 0.5f) * (33.0f / 178.0f) - 0.5f;
    sy = fminf(fmaxf(sy, 0.f), 32.f);
    int p = (int)sy; return p > 29 ? 29 : p;
}
__device__ __forceinline__ float bweight(int x, int q) {
    if (x < 0 || x >= 178) return 0.f;
    float sx = fminf(fmaxf((x + 0.5f) * (43.0f / 178.0f) - 0.5f, 0.f), 42.f);
    int x0 = (int)sx; float fx = sx - (float)x0; int x1 = min(x0 + 1, 42);
    float w = 0.f;
    if (q == x0) w += 1.f - fx;
    if (q == x1) w += fx;
    return w;
}

#define PACK2(d, x)  asm("mov.b64 %0, {%1, %1};" : "=l"(d) : "f"(x))
#define UNPACK2(lo, hi, d) asm("mov.b64 {%0, %1}, %2;" : "=f"(lo), "=f"(hi) : "l"(d))
#define FFMA2(d, a, b) asm("fma.rn.f32x2 %0, %1, %2, %0;" : "+l"(d) : "l"(a), "l"(b))
#define LDS128F(v, ad) asm volatile("ld.shared.v4.f32 {%0,%1,%2,%3}, [%4];" \
    : "=f"(v.x), "=f"(v.y), "=f"(v.z), "=f"(v.w) : "r"(ad))
#define CPASYNC16(dst, src) asm volatile( \
    "cp.async.cg.shared.global [%0], [%1], 16;" :: "r"(dst), "l"(src))
#define CPCOMMIT() asm volatile("cp.async.commit_group;")
#define CPWAIT1()  asm volatile("cp.async.wait_group 1;")
#define CPWAIT0()  asm volatile("cp.async.wait_group 0;")

// ---- prep ------------------------------------------------------------------
__global__ void prep_kernel(const float* __restrict__ w) {
    int t = blockIdx.x * blockDim.x + threadIdx.x;
    if (t < PHI_N) {
        int c  = t & 63;
        int u  = t >> 6;
        int ky = u % 7;  u /= 7;
        int qt = u & 3;
        int j  = u >> 2;
        int q  = q0f(j) + qt;
        const float* wc = w + c * 147 + ky * 7;
        float a = 0.f;
#pragma unroll
        for (int kx = 0; kx < 7; kx++) {
            float ws = wc[kx] + wc[49 + kx] + wc[98 + kx];
            a += ws * bweight(2 * j - 3 + kx, q);
        }
        g_phi[((j * 4 + qt) * 7 + ky) * 64 + c] = a;
    } else if (t < PHI_N + AY_N) {
        int t2 = t - PHI_N;
        int r = t2 / 28, rem = t2 % 28, pt = rem / 7, ky = rem % 7;
        int y = 2 * r - 3 + ky;
        float wgt = 0.f;
        if (y >= 0 && y < 178) {
            float sy = fminf(fmaxf((y + 0.5f) * (33.0f / 178.0f) - 0.5f, 0.f), 32.f);
            int y0 = (int)sy; float fy = sy - (float)y0; int y1 = min(y0 + 1, 32);
            int p = p0f(r) + pt;
            if (p == y0) wgt += 1.f - fy;
            if (p == y1) wgt += fy;
        }
        g_ay[t2] = wgt;
    } else if (t < PHI_N + AY_N + TW_N) {
        int t3 = t - PHI_N - AY_N;
        int k = t3 / 7, n = 1 + t3 % 7;
        float sn, cs;
        sincospif((float)(k * n) * (1.0f / 32.0f), &sn, &cs);
        g_twid[k * 14 + (n - 1) * 2]     = cs;
        g_twid[k * 14 + (n - 1) * 2 + 1] = sn;
    }
}

// ---- spectrogram -----------------------------------------------------------
__global__ void spec_kernel(const float* __restrict__ x, int B) {
    int pq = blockIdx.x;
    int b  = threadIdx.x;
    if (b >= B) return;
    int k  = pq / NFR;
    int fr = pq % NFR;

    const float* s = x + b * SIGLEN + fr * 4;
    float v[8];
    float mean = 0.f;
#pragma unroll
    for (int n = 0; n < 8; n++) { v[n] = s[n]; mean += v[n]; }
    mean *= 0.125f;

    const float* tw = g_twid + k * 14;
    float re = 0.f, im = 0.f;
#pragma unroll
    for (int n = 1; n < 8; n++) {
        float f = v[n] - mean;
        re = fmaf(f, tw[(n - 1) * 2], re);
        im = fmaf(f, -tw[(n - 1) * 2 + 1], im);
    }
    const float SCALE = sqrtf(1.0f / (178.0f * 7.0f));
    g_spec[pq * BMAX + b] = sqrtf(re * re + im * im) * SCALE;
}

// ---- theta: Theta[r][j][tap][c], tap = pt*4+qt -----------------------------
__global__ void theta_kernel() {
    int j  = blockIdx.x;
    int r0 = blockIdx.y * 4;
    int tid = threadIdx.x;
    int c = tid & 63, qt = tid >> 6;

    float f[7];
#pragma unroll
    for (int ky = 0; ky < 7; ky++)
        f[ky] = g_phi[((j * 4 + qt) * 7 + ky) * 64 + c];

#pragma unroll
    for (int rr = 0; rr < 4; rr++) {
        int r = r0 + rr;
        if (r >= CONV_OUT) break;
        const float* ay = g_ay + r * 28;
        float* dst = g_theta + (size_t)(r * 89 + j) * 1024;
#pragma unroll
        for (int pt = 0; pt < 4; pt++) {
            float th = 0.f;
#pragma unroll
            for (int ky = 0; ky < 7; ky++)
                th = fmaf(ay[pt * 7 + ky], f[ky], th);
            dst[(pt * 4 + qt) * 64 + c] = th;
        }
    }
}

// ---- main tap: cp.async Θ pipeline, 512 thr = 8 j x 2 bgroup ---------------
// block = (r, 32 batches); warp w: j = step*8 + (w&7), bgroup = w>>3
__global__ void __launch_bounds__(512, 1)
tap_kernel(const float* __restrict__ bias, int B) {
    extern __shared__ float smem_raw[];   // 64 KB: 2 buffers x 8 slabs x 4KB
    int tid  = threadIdx.x;
    int lane = tid & 31, w = tid >> 5;
    int qd   = lane & 15, bh = lane >> 4;
    int jw   = w & 7, bgrp = w >> 3;

    int item   = blockIdx.x;              // r * 8 + bchunk
    int r      = item >> 3;
    int bchunk = item & 7;
    int b0     = bchunk * 32 + bgrp * 16 + bh * 8;
    int c0     = qd * 4;

    unsigned sb;
    asm("{ .reg .u64 t; cvta.to.shared.u64 t, %1; cvt.u32.u64 %0, t; }"
        : "=r"(sb) : "l"(smem_raw));

    int p0 = p0f(r);
    const float* sprow = g_spec + (p0 * NFR) * BMAX + b0;

    float4 b4 = *(const float4*)(bias + c0);
    unsigned long long bb[4];
    PACK2(bb[0], b4.x); PACK2(bb[1], b4.y);
    PACK2(bb[2], b4.z); PACK2(bb[3], b4.w);

    float acc[4][8];
#pragma unroll
    for (int ci = 0; ci < 4; ci++)
#pragma unroll
        for (int k = 0; k < 8; k++) acc[ci][k] = 0.f;

    const char* tbase = (const char*)(g_theta + (size_t)r * (89 * 1024));

    // stage step s (8 slabs x 4KB = 32KB) across 512 threads, 4 rounds
#define STAGE(s, buf) do {                                                  \
        int _s = (s);                                                       \
        _Pragma("unroll")                                                   \
        for (int r4 = 0; r4 < 4; r4++) {                                    \
            int flat = r4 * 8192 + tid * 16;                                \
            int k = flat >> 12, inner = flat & 4095;                        \
            int jk = _s * 8 + k;                                            \
            if (jk < CONV_OUT)                                              \
                CPASYNC16(sb + (unsigned)((buf) * 32768 + flat),            \
                          tbase + (size_t)jk * 4096 + inner);               \
        }                                                                   \
    } while (0)

    STAGE(0, 0); CPCOMMIT();

    for (int s = 0; s < NSTEP; s++) {
        if (s + 1 < NSTEP) { STAGE(s + 1, (s + 1) & 1); CPCOMMIT(); CPWAIT1(); }
        else               { CPWAIT0(); }
        __syncthreads();

        int j = s * 8 + jw;
        if (j < CONV_OUT) {
            int q0 = q0f(j);
            const float* sp = sprow + q0 * BMAX;
            unsigned slab = sb + (unsigned)(((s & 1) * 32768) + jw * 4096 + qd * 16);

            unsigned long long d[4][4];
#pragma unroll
            for (int ci = 0; ci < 4; ci++)
#pragma unroll
                for (int bi = 0; bi < 4; bi++) d[ci][bi] = bb[ci];

#pragma unroll
            for (int pt = 0; pt < 4; pt++) {
#pragma unroll
                for (int qt = 0; qt < 4; qt++) {
                    int t = pt * 4 + qt;
                    float4 wv;
                    LDS128F(wv, slab + (unsigned)(t * 256));
                    const ulonglong2* s2 =
                        (const ulonglong2*)(sp + (pt * NFR + qt) * BMAX);
                    ulonglong2 u0 = __ldg(s2);
                    ulonglong2 u1 = __ldg(s2 + 1);
                    unsigned long long W0, W1, W2, W3;
                    PACK2(W0, wv.x); PACK2(W1, wv.y);
                    PACK2(W2, wv.z); PACK2(W3, wv.w);
                    FFMA2(d[0][0], W0, u0.x); FFMA2(d[0][1], W0, u0.y);
                    FFMA2(d[0][2], W0, u1.x); FFMA2(d[0][3], W0, u1.y);
                    FFMA2(d[1][0], W1, u0.x); FFMA2(d[1][1], W1, u0.y);
                    FFMA2(d[1][2], W1, u1.x); FFMA2(d[1][3], W1, u1.y);
                    FFMA2(d[2][0], W2, u0.x); FFMA2(d[2][1], W2, u0.y);
                    FFMA2(d[2][2], W2, u1.x); FFMA2(d[2][3], W2, u1.y);
                    FFMA2(d[3][0], W3, u0.x); FFMA2(d[3][1], W3, u0.y);
                    FFMA2(d[3][2], W3, u1.x); FFMA2(d[3][3], W3, u1.y);
                }
            }
#pragma unroll
            for (int ci = 0; ci < 4; ci++)
#pragma unroll
                for (int bi = 0; bi < 4; bi++) {
                    float lo, hi; UNPACK2(lo, hi, d[ci][bi]);
                    acc[ci][2 * bi]     += fmaxf(lo, 0.f);
                    acc[ci][2 * bi + 1] += fmaxf(hi, 0.f);
                }
        }
        __syncthreads();
    }

    // ---- cross-warp reduce: 8 j-streams per bgroup -------------------------
    float4* rs = (float4*)smem_raw;       // [w 16][16 b][16 qd] = 64 KB
#pragma unroll
    for (int bi = 0; bi < 8; bi++)
        rs[w * 256 + (bh * 8 + bi) * 16 + qd] =
            make_float4(acc[0][bi], acc[1][bi], acc[2][bi], acc[3][bi]);
    __syncthreads();

    int bg2 = tid >> 8;                   // bgroup 0/1
    int rem = tid & 255;
    int ob  = rem >> 4;                   // batch within bgroup (0..15)
    int oc4 = rem & 15;                   // c-quad
    float4 v = rs[(bg2 * 8) * 256 + ob * 16 + oc4];
#pragma unroll
    for (int ww = 1; ww < 8; ww++) {
        float4 u = rs[(bg2 * 8 + ww) * 256 + ob * 16 + oc4];
        v.x += u.x; v.y += u.y; v.z += u.z; v.w += u.w;
    }
    int b = bchunk * 32 + bg2 * 16 + ob;
    if (b < B)
        *(float4*)(g_part + ((size_t)r * BMAX + b) * COUT + oc4 * 4) = v;
}

// ---- final: sum partials over r + GAP mean + FC ----------------------------
__global__ void fc_kernel(const float* __restrict__ fw,
                          const float* __restrict__ fb,
                          float* __restrict__ out, int B) {
    __shared__ float sm[4][COUT];
    int b = blockIdx.x;
    int tid = threadIdx.x;
    int c = tid & 63, pg = tid >> 6;
    float sum = 0.f;
    for (int rr = pg; rr < CONV_OUT; rr += 4)
        sum += g_part[((size_t)rr * BMAX + b) * COUT + c];
    sm[pg][c] = sum;
    __syncthreads();
    if (tid < COUT)
        sm[0][tid] += sm[1][tid] + sm[2][tid] + sm[3][tid];
    __syncthreads();
    if (tid < 5) {
        const float inv = 1.0f / (float)(CONV_OUT * CONV_OUT);
        float accv = fb[tid];
#pragma unroll 8
        for (int c2 = 0; c2 < COUT; c2++)
            accv = fmaf(sm[0][c2] * inv, fw[tid * 64 + c2], accv);
        out[b * 5 + tid] = accv;
    }
}

// ---------------------------------------------------------------------------
extern "C" void kernel_launch(void* const* d_in, const int* in_sizes, int n_in,
                              void* d_out, int out_size) {
    const float* x      = (const float*)d_in[0];
    const float* conv_w = (const float*)d_in[1];
    const float* conv_b = (const float*)d_in[2];
    const float* fc_w   = (const float*)d_in[3];
    const float* fc_b   = (const float*)d_in[4];
    float*       out    = (float*)d_out;

    int B = in_sizes[0] / SIGLEN;
    if (B > BMAX) B = BMAX;

    cudaFuncSetAttribute(tap_kernel,
                         cudaFuncAttributeMaxDynamicSharedMemorySize, 65536);

    int prep_total = PHI_N + AY_N + TW_N;
    prep_kernel<<<(prep_total + 255) / 256, 256>>>(conv_w);

    spec_kernel<<<NPQ, 256>>>(x, B);

    dim3 tgrid(89, 23);
    theta_kernel<<<tgrid, 256>>>();

    tap_kernel<<<CONV_OUT * 8, 512, 65536>>>(conv_b, B);

    fc_kernel<<<B, 256>>>(fc_w, fc_b, out, B);
}